// round 14
// baseline (speedup 1.0000x reference)
#include <cuda_runtime.h>
#include <cuda_fp16.h>
#include <cstdint>
#include <cfloat>

// VQ R14: single fp16 hi-pass screen in R8's proven shape (T=512, 1 CTA/SM,
// 16 warps, 128 MMA/warp) + tiny top-2 epilogue per 64-code thread-slice +
// certified exact fp32 rescore (slice-best, or full-slice rescan if 2+ hit).

#define D    64
#define K    512
#define MT   128     // pixels per CTA
#define T    512     // threads per CTA (16 warps)

// SMEM layout (bytes)
#define SX_OFF    0                       // x tile fp32 [d][m]=[64][128]  32KB
#define BA_OFF    32768                   // codebook hi fp16 [512][128B]  64KB
#define SHES_OFF  98304                   // 512 f32
#define SAPX_OFF  100352                  // 128 u32 ordered approx-max
#define SBEST_OFF 100864                  // 128 u64 exact best
#define SMEM_SZ   101888

__device__ __half g_ea[K * D];   // fp16 hi split, permuted+swizzled rows
__device__ float  g_hes[K];      // 0.5*||e||^2
__device__ int    g_mhbits = 0;  // max hes as int bits

// ---------------- helpers ----------------
__device__ __forceinline__ uint32_t smem_u32(const void* p) {
    uint32_t a;
    asm("{ .reg .u64 t; cvta.to.shared.u64 t, %1; cvt.u32.u64 %0, t; }" : "=r"(a) : "l"(p));
    return a;
}
#define MMA_F16(c, a0, a1, a2, a3, b0, b1)                                       \
    asm volatile("mma.sync.aligned.m16n8k16.row.col.f32.f16.f16.f32 "            \
        "{%0,%1,%2,%3},{%4,%5,%6,%7},{%8,%9},{%0,%1,%2,%3};"                     \
        : "+f"((c)[0]), "+f"((c)[1]), "+f"((c)[2]), "+f"((c)[3])                  \
        : "r"(a0), "r"(a1), "r"(a2), "r"(a3), "r"(b0), "r"(b1))

__device__ __forceinline__ void cp16(uint32_t dst, const void* src) {
    asm volatile("cp.async.cg.shared.global [%0], [%1], 16;" :: "r"(dst), "l"(src) : "memory");
}
#define CP_COMMIT() asm volatile("cp.async.commit_group;" ::: "memory")
#define CP_WAIT(n)  asm volatile("cp.async.wait_group %0;" :: "n"(n) : "memory")

__device__ __forceinline__ uint32_t pack2(__half x, __half y) {
    __half2 h = __halves2half2(x, y);
    return *(uint32_t*)&h;
}
__device__ __forceinline__ unsigned ord_enc(float f) {
    unsigned u = __float_as_uint(f);
    return (u & 0x80000000u) ? ~u : (u | 0x80000000u);
}

// exact fp32 rescore: x_p . e_k - 0.5||e_k||^2 (4 independent FMA chains)
__device__ __forceinline__ float rescore(const float* __restrict__ embed,
                                          const float* __restrict__ sx,
                                          const float* __restrict__ shes,
                                          int p, int k) {
    const float4* er = (const float4*)(embed + (size_t)k * D);
    float s0 = 0.f, s1 = 0.f, s2 = 0.f, s3 = 0.f;
    #pragma unroll
    for (int i = 0; i < 16; i++) {
        float4 e4 = er[i];
        s0 = fmaf(sx[(4 * i + 0) * MT + p], e4.x, s0);
        s1 = fmaf(sx[(4 * i + 1) * MT + p], e4.y, s1);
        s2 = fmaf(sx[(4 * i + 2) * MT + p], e4.z, s2);
        s3 = fmaf(sx[(4 * i + 3) * MT + p], e4.w, s3);
    }
    return ((s0 + s1) + (s2 + s3)) - shes[k];
}

// ---------------- prep: hi split codebook (permuted+swizzled), half norms ----
// element d = 32g+16c+8h+2rr+par -> slot ((g<<2)+rr+((k&1)<<2))&7, idx (2c+h)*2+par
__global__ void vq_prep(const float* __restrict__ embed) {
    int k = blockIdx.x, d = threadIdx.x;
    float v = embed[k * D + d];
    __half a = __float2half_rn(v);
    int g = d >> 5, kk = d & 31;
    int rr = (kk >> 1) & 3, h = (kk >> 3) & 1, c = (kk >> 4) & 1, par = kk & 1;
    int slot = ((g << 2) + rr + ((k & 1) << 2)) & 7;
    g_ea[k * 64 + slot * 8 + ((c << 1) + h) * 2 + par] = a;
    float s = v * v;
    #pragma unroll
    for (int o = 16; o > 0; o >>= 1) s += __shfl_down_sync(0xffffffffu, s, o);
    __shared__ float ws[2];
    if ((d & 31) == 0) ws[d >> 5] = s;
    __syncthreads();
    if (d == 0) {
        float hes = 0.5f * (ws[0] + ws[1]);
        g_hes[k] = hes;
        atomicMax(&g_mhbits, __float_as_int(hes));
    }
}

// ---------------- main ----------------
__global__ void __launch_bounds__(T, 1) vq_main(const float* __restrict__ x,
                                                const float* __restrict__ embed,
                                                float* __restrict__ outq,
                                                float* __restrict__ outi) {
    extern __shared__ __align__(1024) char smem[];
    uint32_t sb = smem_u32(smem);
    const int tid = threadIdx.x, wid = tid >> 5, lane = tid & 31;
    const int q = lane >> 2, r = lane & 3;
    const int wm = wid & 7;                  // m-group (16 pixels)
    const int wg = wid >> 3;                 // n-half (tiles 0..31 / 32..63)
    const int n0 = blockIdx.x * MT;
    const int b = n0 >> 12, hw0 = n0 & 4095;

    float* sx = (float*)(smem + SX_OFF);     // [d][128]
    float* shes = (float*)(smem + SHES_OFF);
    unsigned* sapx = (unsigned*)(smem + SAPX_OFF);
    unsigned long long* sbest = (unsigned long long*)(smem + SBEST_OFF);

    // stage hi codebook (64KB) via cp.async
    #pragma unroll
    for (int t = 0; t < 8; t++) {
        int c = tid + t * T;                 // 4096 16B chunks
        cp16(sb + BA_OFF + c * 16, (const char*)g_ea + c * 16);
    }
    CP_COMMIT();

    // stage x tile: sx[c][j] = x[b][c][hw0+j]
    #pragma unroll
    for (int t = 0; t < 4; t++) {
        int i = tid + t * T;
        int c = i >> 5, j4 = (i & 31) << 2;
        float4 v = *(const float4*)(x + (((size_t)(b * D + c)) << 12) + hw0 + j4);
        *(float4*)(sx + c * MT + j4) = v;
    }
    shes[tid] = g_hes[tid];
    if (tid < MT) { sapx[tid] = 0u; sbest[tid] = 0ull; }
    CP_WAIT(0);
    __syncthreads();

    // A hi fragments + ||x||^2 partials: rows m0+q, m0+q+8
    const int m0 = wm * 16;
    const int pa = m0 + q, pb = m0 + q + 8;
    uint32_t Aa[4][4];
    float xp0 = 0.f, xp1 = 0.f;
    #pragma unroll
    for (int cc = 0; cc < 4; cc++) {
        #pragma unroll
        for (int hh = 0; hh < 2; hh++) {
            int k = 16 * cc + 2 * r + 8 * hh;
            float f0a = sx[k * MT + pa],  f1a = sx[(k + 1) * MT + pa];
            float f0b = sx[k * MT + pb],  f1b = sx[(k + 1) * MT + pb];
            xp0 = fmaf(f0a, f0a, fmaf(f1a, f1a, xp0));
            xp1 = fmaf(f0b, f0b, fmaf(f1b, f1b, xp1));
            Aa[cc][2 * hh]     = pack2(__float2half_rn(f0a), __float2half_rn(f1a));
            Aa[cc][2 * hh + 1] = pack2(__float2half_rn(f0b), __float2half_rn(f1b));
        }
    }
    xp0 += __shfl_xor_sync(0xffffffffu, xp0, 1);
    xp0 += __shfl_xor_sync(0xffffffffu, xp0, 2);
    xp1 += __shfl_xor_sync(0xffffffffu, xp1, 1);
    xp1 += __shfl_xor_sync(0xffffffffu, xp1, 2);

    // ---- single screen pass: MMA + top-2 per (row, 64-code thread slice) ----
    float best0 = -FLT_MAX, snd0 = -FLT_MAX;
    float best1 = -FLT_MAX, snd1 = -FLT_MAX;
    int bk0 = 0, bk1 = 0;

    #pragma unroll 1
    for (int tg = 0; tg < 8; tg++) {
        const int t0 = wg * 32 + tg * 4;         // 4 n-tiles (8 codes each)
        float acc[4][4];
        #pragma unroll
        for (int j = 0; j < 4; j++)
            #pragma unroll
            for (int c = 0; c < 4; c++) acc[j][c] = 0.0f;

        #pragma unroll
        for (int j = 0; j < 4; j++) {
            int n = (t0 + j) * 8 + q;
            const char* rowa = smem + BA_OFF + n * 128;
            int so = r + ((n & 1) << 2);
            uint4 va0 = *(const uint4*)(rowa + (so & 7) * 16);
            uint4 va1 = *(const uint4*)(rowa + ((so + 4) & 7) * 16);
            MMA_F16(acc[j], Aa[0][0], Aa[0][1], Aa[0][2], Aa[0][3], va0.x, va0.y);
            MMA_F16(acc[j], Aa[1][0], Aa[1][1], Aa[1][2], Aa[1][3], va0.z, va0.w);
            MMA_F16(acc[j], Aa[2][0], Aa[2][1], Aa[2][2], Aa[2][3], va1.x, va1.y);
            MMA_F16(acc[j], Aa[3][0], Aa[3][1], Aa[3][2], Aa[3][3], va1.z, va1.w);
        }
        #pragma unroll
        for (int j = 0; j < 4; j++) {
            int cb = (t0 + j) * 8 + 2 * r;
            float h0 = shes[cb], h1 = shes[cb + 1];
            // row pa
            {
                float v0 = acc[j][0] - h0, v1 = acc[j][1] - h1;
                float pm = fmaxf(v0, v1), pn = fminf(v0, v1);
                int kp = (v0 >= v1) ? cb : cb + 1;
                bool p = pm > best0;
                snd0 = p ? fmaxf(best0, pn) : fmaxf(snd0, pm);
                bk0 = p ? kp : bk0;
                best0 = fmaxf(best0, pm);
            }
            // row pb
            {
                float v0 = acc[j][2] - h0, v1 = acc[j][3] - h1;
                float pm = fmaxf(v0, v1), pn = fminf(v0, v1);
                int kp = (v0 >= v1) ? cb : cb + 1;
                bool p = pm > best1;
                snd1 = p ? fmaxf(best1, pn) : fmaxf(snd1, pm);
                bk1 = p ? kp : bk1;
                best1 = fmaxf(best1, pm);
            }
        }
    }
    atomicMax(&sapx[pa], ord_enc(best0));
    atomicMax(&sapx[pb], ord_enc(best1));
    __syncthreads();

    // ---- certified exact resolution ----
    {
        float maxEn = sqrtf(2.0f * __int_as_float(g_mhbits));
        #pragma unroll
        for (int i = 0; i < 2; i++) {
            int row = i ? pb : pa;
            float bst = i ? best1 : best0;
            float sn  = i ? snd1 : snd0;
            int   bk  = i ? bk1 : bk0;
            float xn2 = i ? xp1 : xp0;
            unsigned u = sapx[row];
            float smax = __uint_as_float((u & 0x80000000u) ? (u & 0x7fffffffu) : ~u);
            float thr = smax - (2.2e-3f * sqrtf(xn2) * maxEn + 1e-5f);
            if (bst >= thr) {
                if (sn >= thr) {
                    // rare: >=2 candidates in this 64-code slice -> exact rescan
                    for (int tg = 0; tg < 8; tg++) {
                        #pragma unroll
                        for (int j = 0; j < 4; j++) {
                            int cb = (wg * 32 + tg * 4 + j) * 8 + 2 * r;
                            float s0 = rescore(embed, sx, shes, row, cb);
                            atomicMax(&sbest[row],
                                ((unsigned long long)ord_enc(s0) << 32) |
                                (unsigned)(K - 1 - cb));
                            float s1 = rescore(embed, sx, shes, row, cb + 1);
                            atomicMax(&sbest[row],
                                ((unsigned long long)ord_enc(s1) << 32) |
                                (unsigned)(K - 1 - (cb + 1)));
                        }
                    }
                } else {
                    float se = rescore(embed, sx, shes, row, bk);
                    atomicMax(&sbest[row],
                        ((unsigned long long)ord_enc(se) << 32) |
                        (unsigned)(K - 1 - bk));
                }
            }
        }
    }
    __syncthreads();

    // outputs: gathered codebook rows (NHWC) + indices (float)
    #pragma unroll
    for (int t = 0; t < 4; t++) {
        int i = tid + t * T;                      // MT*16 = 2048 float4 writes
        int j = i >> 4, c4 = i & 15;
        int idx = (K - 1) - (int)(sbest[j] & 0xffffffffull);
        float4 v = *(const float4*)(embed + idx * D + (c4 << 2));
        *(float4*)(outq + ((size_t)(n0 + j)) * D + (c4 << 2)) = v;
    }
    if (outi && tid < MT)
        outi[n0 + tid] = (float)((K - 1) - (int)(sbest[tid] & 0xffffffffull));
}

// ---------------------------------------------------------------------------
extern "C" void kernel_launch(void* const* d_in, const int* in_sizes, int n_in,
                              void* d_out, int out_size) {
    const float* x = (const float*)d_in[0];
    const float* embed = (const float*)d_in[1];
    float* out = (float*)d_out;

    const int N = in_sizes[0] / D;
    float* outi = nullptr;
    if (out_size >= N * D + N) outi = out + (size_t)N * D;

    cudaFuncSetAttribute(vq_main, cudaFuncAttributeMaxDynamicSharedMemorySize, SMEM_SZ);
    vq_prep<<<K, D>>>(embed);
    vq_main<<<N / MT, T, SMEM_SZ>>>(x, embed, out, outi);
}